// round 1
// baseline (speedup 1.0000x reference)
#include <cuda_runtime.h>

// qGPS: out[b] = sum_m prod_l eps[samples[b,l], m, l]
// B=4096, L=256, LOCAL_DIM=2, M=64
//
// Strategy:
//  - samples are 0/1 -> pack to bitmasks via __ballot_sync (8 words per batch).
//  - Pairwise-site product table in shared:
//      T2[g][pat][mh] : float2 { T(m=mh), T(m=mh+32) }
//      T(m) = eps[pat&1, m, 2g] * eps[(pat>>1)&1, m, 2g+1]
//    128 groups x 4 patterns x 32 float2 = 128 KB shared (dynamic, attr raised).
//  - One warp per batch: 128 conflict-free LDS.64 reads + FMUL chains (4 accumulators),
//    warp shuffle-reduce over m, single STG per batch.

#define NB 4096
#define NL 256
#define NM 64
#define NG 128           // NL / 2 pair-groups
#define THREADS 512
#define BLOCKS 148
#define SMEM_BYTES (NG * 4 * 32 * (int)sizeof(float2))   // 131072

__global__ __launch_bounds__(THREADS, 1)
void qgps_kernel(const int* __restrict__ samples,
                 const float* __restrict__ eps,
                 float* __restrict__ out)
{
    extern __shared__ float2 T2[];   // [(g*4 + pat)*32 + mh]
    const int tid = threadIdx.x;

    // ---- Phase 1: build pair-product table (coalesced float2 reads of eps) ----
    // eps[s][m][l], float2 view: index (s*NM + m)*(NL/2) + g  -> {eps[s,m,2g], eps[s,m,2g+1]}
    const float2* e2 = (const float2*)eps;
    for (int item = tid; item < NG * 32; item += THREADS) {
        int mh = item >> 7;        // 0..31   (warp lanes sweep g -> coalesced)
        int g  = item & (NG - 1);  // 0..127
        float2 e0a = e2[(0 * NM + mh     ) * (NL / 2) + g];
        float2 e1a = e2[(1 * NM + mh     ) * (NL / 2) + g];
        float2 e0b = e2[(0 * NM + mh + 32) * (NL / 2) + g];
        float2 e1b = e2[(1 * NM + mh + 32) * (NL / 2) + g];
#pragma unroll
        for (int p = 0; p < 4; p++) {
            float xa = (p & 1) ? e1a.x : e0a.x;   // site l = 2g
            float ya = (p & 2) ? e1a.y : e0a.y;   // site l = 2g+1
            float xb = (p & 1) ? e1b.x : e0b.x;
            float yb = (p & 2) ? e1b.y : e0b.y;
            T2[(g * 4 + p) * 32 + mh] = make_float2(xa * ya, xb * yb);
        }
    }
    __syncthreads();

    // ---- Phase 2: one warp per batch ----
    const int lane   = tid & 31;
    const int gwarp  = blockIdx.x * (THREADS / 32) + (tid >> 5);
    const int nwarps = gridDim.x * (THREADS / 32);

    for (int b = gwarp; b < NB; b += nwarps) {
        const int* sb = samples + b * NL;

        unsigned w[8];
#pragma unroll
        for (int j = 0; j < 8; j++)
            w[j] = __ballot_sync(0xffffffffu, sb[j * 32 + lane] != 0);

        float p0 = 1.0f, p1 = 1.0f, q0 = 1.0f, q1 = 1.0f;
#pragma unroll
        for (int j = 0; j < 8; j++) {
            unsigned word = w[j];
#pragma unroll
            for (int k = 0; k < 16; k += 2) {
                int g = j * 16 + k;
                unsigned pa = (word >> (2 * k))     & 3u;
                unsigned pb = (word >> (2 * k + 2)) & 3u;
                float2 ta = T2[(g * 4 + pa) * 32 + lane];
                float2 tb = T2[((g + 1) * 4 + pb) * 32 + lane];
                p0 *= ta.x; p1 *= ta.y;
                q0 *= tb.x; q1 *= tb.y;
            }
        }
        float s = p0 * q0 + p1 * q1;   // lane holds m=lane and m=lane+32
#pragma unroll
        for (int off = 16; off; off >>= 1)
            s += __shfl_xor_sync(0xffffffffu, s, off);
        if (lane == 0) out[b] = s;
    }
}

extern "C" void kernel_launch(void* const* d_in, const int* in_sizes, int n_in,
                              void* d_out, int out_size)
{
    const int*   samples = (const int*)d_in[0];
    const float* eps     = (const float*)d_in[1];
    // defensive: identify by element count if order is swapped
    if (n_in >= 2 && in_sizes[0] == 2 * NM * NL && in_sizes[1] == NB * NL) {
        samples = (const int*)d_in[1];
        eps     = (const float*)d_in[0];
    }
    cudaFuncSetAttribute(qgps_kernel,
                         cudaFuncAttributeMaxDynamicSharedMemorySize, SMEM_BYTES);
    qgps_kernel<<<BLOCKS, THREADS, SMEM_BYTES>>>(samples, eps, (float*)d_out);
}

// round 2
// speedup vs baseline: 1.4314x; 1.4314x over previous
#include <cuda_runtime.h>

// qGPS: out[b] = sum_m prod_l eps[samples[b,l], m, l]
// B=4096, L=256, LOCAL_DIM=2, M=64
//
//  - samples 0/1 -> bitmasks via __ballot_sync (8 words per batch).
//  - Pair-site product table in shared, XOR-swizzled to keep BOTH the
//    build-time STS (lanes sweep g) and the read-time LDS (lanes sweep mh)
//    bank-conflict-free:
//      idx(g,pat,mh) = (g*4+pat)*32 + (mh ^ (g & 31))
//      value: float2 { T(m=mh), T(m=mh+32) },  T(m)=eps[p&1,m,2g]*eps[p>>1,m,2g+1]
//    128 groups x 4 patterns x 32 float2 = 128 KB dynamic shared.
//  - One warp per batch: 128 conflict-free LDS.64 + 4 independent FMUL chains,
//    shuffle-reduce over m, one STG.

#define NB 4096
#define NL 256
#define NM 64
#define NG 128           // NL/2 pair-groups
#define THREADS 1024
#define BLOCKS 148
#define SMEM_BYTES (NG * 4 * 32 * (int)sizeof(float2))   // 131072

__global__ __launch_bounds__(THREADS, 1)
void qgps_kernel(const int* __restrict__ samples,
                 const float* __restrict__ eps,
                 float* __restrict__ out)
{
    extern __shared__ float2 T2[];
    const int tid  = threadIdx.x;
    const int lane = tid & 31;

    // ---- Phase 1: build table. Lanes sweep g -> coalesced LDG; swizzled STS. ----
    // eps float2 view: e2[(s*NM + m)*(NL/2) + g] = {eps[s,m,2g], eps[s,m,2g+1]}
    const float2* e2 = (const float2*)eps;
#pragma unroll
    for (int it = 0; it < (NG * 32) / THREADS; it++) {
        int item = tid + it * THREADS;
        int mh = item >> 7;        // 0..31, constant within a warp
        int g  = item & (NG - 1);  // lanes -> consecutive g
        float2 e0a = e2[(0 * NM + mh     ) * (NL / 2) + g];
        float2 e1a = e2[(1 * NM + mh     ) * (NL / 2) + g];
        float2 e0b = e2[(0 * NM + mh + 32) * (NL / 2) + g];
        float2 e1b = e2[(1 * NM + mh + 32) * (NL / 2) + g];
        int sw = mh ^ (g & 31);    // swizzled mh slot
#pragma unroll
        for (int p = 0; p < 4; p++) {
            float xa = (p & 1) ? e1a.x : e0a.x;
            float ya = (p & 2) ? e1a.y : e0a.y;
            float xb = (p & 1) ? e1b.x : e0b.x;
            float yb = (p & 2) ? e1b.y : e0b.y;
            T2[(g * 4 + p) * 32 + sw] = make_float2(xa * ya, xb * yb);
        }
    }
    __syncthreads();

    // ---- Phase 2: one warp per batch ----
    const int gwarp  = blockIdx.x * (THREADS / 32) + (tid >> 5);
    const int nwarps = BLOCKS * (THREADS / 32);

    for (int b = gwarp; b < NB; b += nwarps) {
        const int* sb = samples + b * NL;

        unsigned w[8];
#pragma unroll
        for (int j = 0; j < 8; j++)
            w[j] = __ballot_sync(0xffffffffu, sb[j * 32 + lane] != 0);

        float p0 = 1.0f, p1 = 1.0f, q0 = 1.0f, q1 = 1.0f;
#pragma unroll
        for (int j = 0; j < 8; j++) {
            unsigned word = w[j];
#pragma unroll
            for (int k = 0; k < 16; k += 2) {
                int g0 = j * 16 + k;
                int g1 = g0 + 1;
                unsigned pa = (word >> (2 * k))     & 3u;
                unsigned pb = (word >> (2 * k + 2)) & 3u;
                float2 ta = T2[(g0 * 4 + pa) * 32 + (lane ^ (g0 & 31))];
                float2 tb = T2[(g1 * 4 + pb) * 32 + (lane ^ (g1 & 31))];
                p0 *= ta.x; p1 *= ta.y;
                q0 *= tb.x; q1 *= tb.y;
            }
        }
        float s = p0 * q0 + p1 * q1;   // lane covers m=lane and m=lane+32
#pragma unroll
        for (int off = 16; off; off >>= 1)
            s += __shfl_xor_sync(0xffffffffu, s, off);
        if (lane == 0) out[b] = s;
    }
}

extern "C" void kernel_launch(void* const* d_in, const int* in_sizes, int n_in,
                              void* d_out, int out_size)
{
    const int*   samples = (const int*)d_in[0];
    const float* eps     = (const float*)d_in[1];
    if (n_in >= 2 && in_sizes[0] == 2 * NM * NL && in_sizes[1] == NB * NL) {
        samples = (const int*)d_in[1];
        eps     = (const float*)d_in[0];
    }
    cudaFuncSetAttribute(qgps_kernel,
                         cudaFuncAttributeMaxDynamicSharedMemorySize, SMEM_BYTES);
    qgps_kernel<<<BLOCKS, THREADS, SMEM_BYTES>>>(samples, eps, (float*)d_out);
}

// round 6
// speedup vs baseline: 1.7433x; 1.2179x over previous
#include <cuda_runtime.h>
#include <cuda_bf16.h>
#include <stdint.h>

// qGPS: out[b] = sum_m prod_l eps[samples[b,l], m, l],  B=4096 L=256 D=2 M=64
//
// log-domain GEMM on HMMA (mma.sync bf16, baseline ISA -> compiles for compute_103):
//   acc[b,m] = sum_l s_l * d[m,l],  d = log2(eps1/eps0) split bf16 hi+lo
//   out[b]   = sum_m exp2(base2[m] + acc[b,m]),  base2[m] = sum_l log2 eps0[m,l]
// 64 CTAs x 128 threads; 4 warps x M=16 rows = 64 batches per CTA.

#define NB 4096
#define NL 256
#define NM 64

__device__ __align__(16) __nv_bfloat16 g_dhi[NM * NL];
__device__ __align__(16) __nv_bfloat16 g_dlo[NM * NL];
__device__ float g_base2[NM];

// ---------------- kernel 1: prep ----------------
__global__ void prep_kernel(const float* __restrict__ eps)
{
    __shared__ float red[NL];
    int m = blockIdx.x, l = threadIdx.x;
    float e0 = eps[m * NL + l];
    float e1 = eps[NM * NL + m * NL + l];
    float l0 = log2f(e0);
    float d  = log2f(e1) - l0;
    __nv_bfloat16 hi = __float2bfloat16(d);
    g_dhi[m * NL + l] = hi;
    g_dlo[m * NL + l] = __float2bfloat16(d - __bfloat162float(hi));
    red[l] = l0;
    __syncthreads();
#pragma unroll
    for (int s = NL / 2; s > 0; s >>= 1) {
        if (l < s) red[l] += red[l + s];
        __syncthreads();
    }
    if (l == 0) g_base2[m] = red[0];
}

// ---------------- kernel 2: HMMA GEMM + exp2 epilogue ----------------
// smem: A (64 rows x 512B swz) [0,32K)  Bh [32K,64K)  Bl [64K,96K)  base2 [96K,+256)
#define SM_A  0
#define SM_BH 32768
#define SM_BL 65536
#define SM_B2 98304
#define SMEM2 98816

__device__ __forceinline__ uint32_t swz(int row, int byte_in_row) {
    return (uint32_t)(row * 512 + (byte_in_row ^ ((row & 7) << 4)));
}

__device__ __forceinline__ void mma16816(float* d, uint32_t a0, uint32_t a1,
                                         uint32_t a2, uint32_t a3,
                                         uint32_t b0, uint32_t b1)
{
    asm volatile(
        "mma.sync.aligned.m16n8k16.row.col.f32.bf16.bf16.f32 "
        "{%0,%1,%2,%3}, {%4,%5,%6,%7}, {%8,%9}, {%0,%1,%2,%3};"
        : "+f"(d[0]), "+f"(d[1]), "+f"(d[2]), "+f"(d[3])
        : "r"(a0), "r"(a1), "r"(a2), "r"(a3), "r"(b0), "r"(b1));
}

__global__ __launch_bounds__(128, 1)
void qgps_hmma_kernel(const int* __restrict__ samples, float* __restrict__ out)
{
    extern __shared__ char smem[];
    const int tid  = threadIdx.x;
    const int wid  = tid >> 5;         // 0..3
    const int lane = tid & 31;
    const int bid  = blockIdx.x;       // 64 CTAs x 64 batches

    // ---- fill A: samples -> bf16 {0,1}, swizzled (64 rows x 256 cols) ----
    {
        const int4* src = (const int4*)(samples + (size_t)bid * 64 * NL);
#pragma unroll
        for (int it = 0; it < 16; it++) {
            int c   = tid + it * 128;          // 16B chunk id, 0..2047
            int row = c >> 5;
            int cb  = (c & 31) * 16;
            int4 sa = src[2 * c], sb = src[2 * c + 1];
            uint32_t w0 = (uint32_t)sa.x * 0x3F80u + (uint32_t)sa.y * 0x3F800000u;
            uint32_t w1 = (uint32_t)sa.z * 0x3F80u + (uint32_t)sa.w * 0x3F800000u;
            uint32_t w2 = (uint32_t)sb.x * 0x3F80u + (uint32_t)sb.y * 0x3F800000u;
            uint32_t w3 = (uint32_t)sb.z * 0x3F80u + (uint32_t)sb.w * 0x3F800000u;
            *(uint4*)(smem + SM_A + swz(row, cb)) = make_uint4(w0, w1, w2, w3);
        }
    }
    // ---- fill Bh/Bl (64 rows x 256 cols each), swizzled ----
    {
        const uint4* hs = (const uint4*)g_dhi;
        const uint4* ls = (const uint4*)g_dlo;
#pragma unroll
        for (int it = 0; it < 16; it++) {
            int c   = tid + it * 128;
            int row = c >> 5;
            int cb  = (c & 31) * 16;
            uint32_t a = swz(row, cb);
            *(uint4*)(smem + SM_BH + a) = hs[c];
            *(uint4*)(smem + SM_BL + a) = ls[c];
        }
    }
    if (tid < NM) *(float*)(smem + SM_B2 + tid * 4) = g_base2[tid];
    __syncthreads();

    // ---- MMA: each warp one M=16 tile, full K=256, N=64, hi+lo chained ----
    const int qrow = lane >> 2;        // 0..7
    const int qk   = (lane & 3) * 4;   // k-pair byte offset
    const int ar0  = wid * 16 + qrow;  // < 64
    const int ar1  = ar0 + 8;

    float acc[8][4];
#pragma unroll
    for (int n = 0; n < 8; n++)
#pragma unroll
        for (int j = 0; j < 4; j++) acc[n][j] = 0.0f;

#pragma unroll
    for (int kk = 0; kk < 16; kk++) {
        int kb = kk * 32 + qk;
        uint32_t a0 = *(const uint32_t*)(smem + SM_A + swz(ar0, kb));
        uint32_t a1 = *(const uint32_t*)(smem + SM_A + swz(ar1, kb));
        uint32_t a2 = *(const uint32_t*)(smem + SM_A + swz(ar0, kb + 16));
        uint32_t a3 = *(const uint32_t*)(smem + SM_A + swz(ar1, kb + 16));
#pragma unroll
        for (int n = 0; n < 8; n++) {
            int br = n * 8 + qrow;     // < 64
            uint32_t bh0 = *(const uint32_t*)(smem + SM_BH + swz(br, kb));
            uint32_t bh1 = *(const uint32_t*)(smem + SM_BH + swz(br, kb + 16));
            mma16816(acc[n], a0, a1, a2, a3, bh0, bh1);
            uint32_t bl0 = *(const uint32_t*)(smem + SM_BL + swz(br, kb));
            uint32_t bl1 = *(const uint32_t*)(smem + SM_BL + swz(br, kb + 16));
            mma16816(acc[n], a0, a1, a2, a3, bl0, bl1);
        }
    }

    // ---- epilogue: exp2(acc + base2) and reduce over m ----
    const float* b2 = (const float*)(smem + SM_B2);
    float s0 = 0.0f, s1 = 0.0f;
#pragma unroll
    for (int n = 0; n < 8; n++) {
        int c0 = n * 8 + (lane & 3) * 2;
        float ba = b2[c0], bb = b2[c0 + 1];
        float e0, e1, e2, e3;
        asm("ex2.approx.ftz.f32 %0, %1;" : "=f"(e0) : "f"(acc[n][0] + ba));
        asm("ex2.approx.ftz.f32 %0, %1;" : "=f"(e1) : "f"(acc[n][1] + bb));
        asm("ex2.approx.ftz.f32 %0, %1;" : "=f"(e2) : "f"(acc[n][2] + ba));
        asm("ex2.approx.ftz.f32 %0, %1;" : "=f"(e3) : "f"(acc[n][3] + bb));
        s0 += e0 + e1;
        s1 += e2 + e3;
    }
#pragma unroll
    for (int off = 1; off <= 2; off <<= 1) {
        s0 += __shfl_xor_sync(0xffffffffu, s0, off);
        s1 += __shfl_xor_sync(0xffffffffu, s1, off);
    }
    if ((lane & 3) == 0) {
        int b = bid * 64 + wid * 16 + qrow;   // < 4096
        out[b]     = s0;
        out[b + 8] = s1;
    }
}

extern "C" void kernel_launch(void* const* d_in, const int* in_sizes, int n_in,
                              void* d_out, int out_size)
{
    const int*   samples = (const int*)d_in[0];
    const float* eps     = (const float*)d_in[1];
    if (n_in >= 2 && in_sizes[0] == 2 * NM * NL && in_sizes[1] == NB * NL) {
        samples = (const int*)d_in[1];
        eps     = (const float*)d_in[0];
    }
    prep_kernel<<<NM, NL>>>(eps);
    cudaFuncSetAttribute(qgps_hmma_kernel,
                         cudaFuncAttributeMaxDynamicSharedMemorySize, SMEM2);
    qgps_hmma_kernel<<<NB / 64, 128, SMEM2>>>(samples, (float*)d_out);
}

// round 7
// speedup vs baseline: 2.0932x; 1.2007x over previous
#include <cuda_runtime.h>
#include <cuda_bf16.h>
#include <stdint.h>

// qGPS: out[b] = sum_m prod_l eps[samples[b,l], m, l],  B=4096 L=256 D=2 M=64
//
// log-domain GEMM on HMMA:
//   acc[b,m] = sum_l s_l * d[m,l],  d = log2(eps1/eps0) split bf16 hi+lo
//   out[b]   = sum_m exp2(base2[m] + acc[b,m])
// 128 CTAs x 256 threads; 8 warps each own (16-batch row tile) x (16-col N quarter).

#define NB 4096
#define NL 256
#define NM 64

__device__ __align__(16) __nv_bfloat16 g_dhi[NM * NL];
__device__ __align__(16) __nv_bfloat16 g_dlo[NM * NL];
__device__ float g_base2[NM];

// ---------------- kernel 1: prep ----------------
__global__ __launch_bounds__(NL, 1) void prep_kernel(const float* __restrict__ eps)
{
    __shared__ float wsum[8];
    int m = blockIdx.x, l = threadIdx.x;
    float e0 = eps[m * NL + l];
    float e1 = eps[NM * NL + m * NL + l];
    float l0 = log2f(e0);
    float d  = log2f(e1) - l0;
    __nv_bfloat16 hi = __float2bfloat16(d);
    g_dhi[m * NL + l] = hi;
    g_dlo[m * NL + l] = __float2bfloat16(d - __bfloat162float(hi));
#pragma unroll
    for (int off = 16; off; off >>= 1)
        l0 += __shfl_xor_sync(0xffffffffu, l0, off);
    if ((l & 31) == 0) wsum[l >> 5] = l0;
    __syncthreads();
    if (l == 0) {
        float s = 0.0f;
#pragma unroll
        for (int j = 0; j < 8; j++) s += wsum[j];
        g_base2[m] = s;
    }
}

// ---------------- kernel 2: HMMA GEMM + exp2 epilogue ----------------
// smem: A (32 rows x 512B swz) [0,16K)  Bh [16K,48K)  Bl [48K,80K)
//       base2 [80K,+256)  part [80K+256, +512)
#define SM_A   0
#define SM_BH  16384
#define SM_BL  49152
#define SM_B2  81920
#define SM_PT  82176
#define SMEM2  82688

__device__ __forceinline__ uint32_t swz(int row, int byte_in_row) {
    return (uint32_t)(row * 512 + (byte_in_row ^ ((row & 7) << 4)));
}

__device__ __forceinline__ void mma16816(float* d, uint32_t a0, uint32_t a1,
                                         uint32_t a2, uint32_t a3,
                                         uint32_t b0, uint32_t b1)
{
    asm volatile(
        "mma.sync.aligned.m16n8k16.row.col.f32.bf16.bf16.f32 "
        "{%0,%1,%2,%3}, {%4,%5,%6,%7}, {%8,%9}, {%0,%1,%2,%3};"
        : "+f"(d[0]), "+f"(d[1]), "+f"(d[2]), "+f"(d[3])
        : "r"(a0), "r"(a1), "r"(a2), "r"(a3), "r"(b0), "r"(b1));
}

__global__ __launch_bounds__(256, 1)
void qgps_hmma_kernel(const int* __restrict__ samples, float* __restrict__ out)
{
    extern __shared__ char smem[];
    const int tid  = threadIdx.x;
    const int wid  = tid >> 5;         // 0..7
    const int lane = tid & 31;
    const int bid  = blockIdx.x;       // 128 CTAs x 32 batches

    // ---- fill A: samples -> bf16 {0,1}, swizzled (32 rows x 256 cols) ----
    {
        const int4* src = (const int4*)(samples + (size_t)bid * 32 * NL);
#pragma unroll
        for (int it = 0; it < 4; it++) {
            int c   = tid + it * 256;          // 16B chunk id, 0..1023
            int row = c >> 5;
            int cb  = (c & 31) * 16;
            int4 sa = src[2 * c], sb = src[2 * c + 1];
            uint32_t w0 = (uint32_t)sa.x * 0x3F80u + (uint32_t)sa.y * 0x3F800000u;
            uint32_t w1 = (uint32_t)sa.z * 0x3F80u + (uint32_t)sa.w * 0x3F800000u;
            uint32_t w2 = (uint32_t)sb.x * 0x3F80u + (uint32_t)sb.y * 0x3F800000u;
            uint32_t w3 = (uint32_t)sb.z * 0x3F80u + (uint32_t)sb.w * 0x3F800000u;
            *(uint4*)(smem + SM_A + swz(row, cb)) = make_uint4(w0, w1, w2, w3);
        }
    }
    // ---- fill Bh/Bl (64 rows x 256 cols each), swizzled ----
    {
        const uint4* hs = (const uint4*)g_dhi;
        const uint4* ls = (const uint4*)g_dlo;
#pragma unroll
        for (int it = 0; it < 8; it++) {
            int c   = tid + it * 256;          // 0..2047
            int row = c >> 5;
            int cb  = (c & 31) * 16;
            uint32_t a = swz(row, cb);
            *(uint4*)(smem + SM_BH + a) = hs[c];
            *(uint4*)(smem + SM_BL + a) = ls[c];
        }
    }
    if (tid < NM) *(float*)(smem + SM_B2 + tid * 4) = g_base2[tid];
    __syncthreads();

    // ---- MMA: warp = (row tile rt = wid&1) x (N quarter nh = wid>>1) ----
    const int rt   = wid & 1;
    const int nh   = wid >> 1;         // 0..3
    const int qrow = lane >> 2;        // 0..7
    const int qk   = (lane & 3) * 4;
    const int ar0  = rt * 16 + qrow;   // < 32
    const int ar1  = ar0 + 8;

    float acc[2][4];
#pragma unroll
    for (int j = 0; j < 2; j++)
#pragma unroll
        for (int k = 0; k < 4; k++) acc[j][k] = 0.0f;

#pragma unroll
    for (int kk = 0; kk < 16; kk++) {
        int kb = kk * 32 + qk;
        uint32_t a0 = *(const uint32_t*)(smem + SM_A + swz(ar0, kb));
        uint32_t a1 = *(const uint32_t*)(smem + SM_A + swz(ar1, kb));
        uint32_t a2 = *(const uint32_t*)(smem + SM_A + swz(ar0, kb + 16));
        uint32_t a3 = *(const uint32_t*)(smem + SM_A + swz(ar1, kb + 16));
#pragma unroll
        for (int j = 0; j < 2; j++) {
            int br = (nh * 2 + j) * 8 + qrow;   // < 64
            uint32_t bh0 = *(const uint32_t*)(smem + SM_BH + swz(br, kb));
            uint32_t bh1 = *(const uint32_t*)(smem + SM_BH + swz(br, kb + 16));
            mma16816(acc[j], a0, a1, a2, a3, bh0, bh1);
            uint32_t bl0 = *(const uint32_t*)(smem + SM_BL + swz(br, kb));
            uint32_t bl1 = *(const uint32_t*)(smem + SM_BL + swz(br, kb + 16));
            mma16816(acc[j], a0, a1, a2, a3, bl0, bl1);
        }
    }

    // ---- epilogue: exp2(acc + base2), partial reduce over this warp's 16 m ----
    const float* b2 = (const float*)(smem + SM_B2);
    float s0 = 0.0f, s1 = 0.0f;
#pragma unroll
    for (int j = 0; j < 2; j++) {
        int c0 = (nh * 2 + j) * 8 + (lane & 3) * 2;
        float ba = b2[c0], bb = b2[c0 + 1];
        float e0, e1, e2, e3;
        asm("ex2.approx.ftz.f32 %0, %1;" : "=f"(e0) : "f"(acc[j][0] + ba));
        asm("ex2.approx.ftz.f32 %0, %1;" : "=f"(e1) : "f"(acc[j][1] + bb));
        asm("ex2.approx.ftz.f32 %0, %1;" : "=f"(e2) : "f"(acc[j][2] + ba));
        asm("ex2.approx.ftz.f32 %0, %1;" : "=f"(e3) : "f"(acc[j][3] + bb));
        s0 += e0 + e1;
        s1 += e2 + e3;
    }
#pragma unroll
    for (int off = 1; off <= 2; off <<= 1) {
        s0 += __shfl_xor_sync(0xffffffffu, s0, off);
        s1 += __shfl_xor_sync(0xffffffffu, s1, off);
    }
    float* part = (float*)(smem + SM_PT);   // [32 batches][4 quarters]
    if ((lane & 3) == 0) {
        part[(rt * 16 + qrow)     * 4 + nh] = s0;
        part[(rt * 16 + qrow + 8) * 4 + nh] = s1;
    }
    __syncthreads();
    if (tid < 32) {
        float s = part[tid * 4] + part[tid * 4 + 1] + part[tid * 4 + 2] + part[tid * 4 + 3];
        out[bid * 32 + tid] = s;
    }
}

extern "C" void kernel_launch(void* const* d_in, const int* in_sizes, int n_in,
                              void* d_out, int out_size)
{
    const int*   samples = (const int*)d_in[0];
    const float* eps     = (const float*)d_in[1];
    if (n_in >= 2 && in_sizes[0] == 2 * NM * NL && in_sizes[1] == NB * NL) {
        samples = (const int*)d_in[1];
        eps     = (const float*)d_in[0];
    }
    prep_kernel<<<NM, NL>>>(eps);
    cudaFuncSetAttribute(qgps_hmma_kernel,
                         cudaFuncAttributeMaxDynamicSharedMemorySize, SMEM2);
    qgps_hmma_kernel<<<NB / 32, 256, SMEM2>>>(samples, (float*)d_out);
}